// round 7
// baseline (speedup 1.0000x reference)
#include <cuda_runtime.h>
#include <cuda_bf16.h>
#include <cstdint>

#define NNODES 20000
#define NEDGES 320000
#define FNODE  64
#define FEDGE  16
#define HIDN   300
#define NGRAPH 128

typedef unsigned long long ull;

// ---------------- scratch (device globals) ----------------
__device__ float g_h0[NEDGES * HIDN];
__device__ float g_hA[NEDGES * HIDN];          // t ping
__device__ float g_hB[NEDGES * HIDN];          // t pong
__device__ __nv_bfloat16 g_Ah[NEDGES * 320];   // A operand hi (current layer)
__device__ __nv_bfloat16 g_Al[NEDGES * 320];   // A operand lo
__device__ float g_a [NNODES * HIDN];          // u = segsum(t)
__device__ float g_s [NNODES * HIDN];          // final node message
__device__ float g_pool[NGRAPH * HIDN];
__device__ __nv_bfloat16 g_Wh [3 * 384 * 320]; // conv W^T hi [l][n][k], zero-pad
__device__ __nv_bfloat16 g_Wl [3 * 384 * 320];
__device__ __nv_bfloat16 g_WIh[384 * 320];     // init W^T hi
__device__ __nv_bfloat16 g_WIl[384 * 320];
__device__ int g_cnt [NNODES];
__device__ int g_ptr [NNODES + 1];
__device__ int g_fill[NNODES];
__device__ int g_eid [NEDGES];

__device__ __forceinline__ float* hbuf(int s) {
    return (s == 0) ? g_h0 : ((s == 1) ? g_hA : g_hB);
}

// ---------------- helpers ----------------
__device__ __forceinline__ float4 ld4(const float* p) { return *reinterpret_cast<const float4*>(p); }
__device__ __forceinline__ void   st4(float* p, float4 v) { *reinterpret_cast<float4*>(p) = v; }
__device__ __forceinline__ float  frelu(float x) { return x > 0.f ? x : 0.f; }

__device__ __forceinline__ ull fma2(ull a, ull b, ull c) {
    ull d;
    asm("fma.rn.f32x2 %0, %1, %2, %3;" : "=l"(d) : "l"(a), "l"(b), "l"(c));
    return d;
}
__device__ __forceinline__ void unpack2(ull v, float& lo, float& hi) {
    asm("mov.b64 {%0, %1}, %2;" : "=f"(lo), "=f"(hi) : "l"(v));
}
__device__ __forceinline__ uint32_t smem_u32(const void* p) {
    uint32_t a;
    asm("{ .reg .u64 t; cvta.to.shared.u64 t, %1; cvt.u32.u64 %0, t; }" : "=r"(a) : "l"(p));
    return a;
}
__device__ __forceinline__ uint32_t sw128(uint32_t o) { return o ^ ((o >> 3) & 0x70); }
__device__ __forceinline__ uint32_t sw64 (uint32_t o) { return o ^ ((o >> 3) & 0x30); }

__device__ __forceinline__ void ldsm4(uint32_t* r, uint32_t a) {
    asm volatile("ldmatrix.sync.aligned.m8n8.x4.shared.b16 {%0,%1,%2,%3}, [%4];"
                 : "=r"(r[0]), "=r"(r[1]), "=r"(r[2]), "=r"(r[3]) : "r"(a));
}
__device__ __forceinline__ void mma_bf(float* d, const uint32_t* a, const uint32_t* b) {
    asm volatile("mma.sync.aligned.m16n8k16.row.col.f32.bf16.bf16.f32 "
                 "{%0,%1,%2,%3}, {%4,%5,%6,%7}, {%8,%9}, {%0,%1,%2,%3};"
                 : "+f"(d[0]), "+f"(d[1]), "+f"(d[2]), "+f"(d[3])
                 : "r"(a[0]), "r"(a[1]), "r"(a[2]), "r"(a[3]), "r"(b[0]), "r"(b[1]));
}
#define CPA16(dst, src) asm volatile("cp.async.cg.shared.global [%0], [%1], 16;" :: "r"(dst), "l"(src))
#define CPA_COMMIT()    asm volatile("cp.async.commit_group;" ::: "memory")
#define CPA_WAIT0()     asm volatile("cp.async.wait_group 0;" ::: "memory")
#define CPA_WAIT1()     asm volatile("cp.async.wait_group 1;" ::: "memory")

__device__ __forceinline__ void split_pack(float v0, float v1, uint32_t& hi, uint32_t& lo) {
    __nv_bfloat162 h, l;
    h.x = __float2bfloat16(v0); h.y = __float2bfloat16(v1);
    l.x = __float2bfloat16(v0 - __bfloat162float(h.x));
    l.y = __float2bfloat16(v1 - __bfloat162float(h.y));
    hi = *reinterpret_cast<uint32_t*>(&h);
    lo = *reinterpret_cast<uint32_t*>(&l);
}

// ---------------- preprocessing ----------------
__global__ void k_pre(const float* __restrict__ Wc, const float* __restrict__ Wi) {
    int t = blockIdx.x * blockDim.x + threadIdx.x;
    if (t < NNODES) g_cnt[t] = 0;
    if (t < NGRAPH * HIDN) g_pool[t] = 0.f;
    if (t < 122880) {
        int n = t / 320, k = t % 320;
        float v = (n < HIDN && k < 80) ? Wi[k * HIDN + n] : 0.f;
        __nv_bfloat16 bh = __float2bfloat16(v);
        g_WIh[t] = bh;
        g_WIl[t] = __float2bfloat16(v - __bfloat162float(bh));
    }
    if (t < 3 * 122880) {
        int l = t / 122880, r2 = t % 122880;
        int n = r2 / 320, k = r2 % 320;
        float v = (n < HIDN && k < HIDN) ? Wc[l * HIDN * HIDN + k * HIDN + n] : 0.f;
        __nv_bfloat16 bh = __float2bfloat16(v);
        g_Wh[t] = bh;
        g_Wl[t] = __float2bfloat16(v - __bfloat162float(bh));
    }
}

__global__ void k_hist(const int* __restrict__ coli) {
    int e = blockIdx.x * blockDim.x + threadIdx.x;
    if (e < NEDGES) atomicAdd(&g_cnt[coli[e]], 1);
}

__global__ void k_scan() {
    __shared__ int sh[1024];
    int tid = threadIdx.x;
    int carry = 0;
    const int CH = (NNODES + 1023) / 1024;
    for (int c = 0; c < CH; ++c) {
        int i = c * 1024 + tid;
        int v = (i < NNODES) ? g_cnt[i] : 0;
        sh[tid] = v;
        __syncthreads();
        for (int off = 1; off < 1024; off <<= 1) {
            int t = (tid >= off) ? sh[tid - off] : 0;
            __syncthreads();
            sh[tid] += t;
            __syncthreads();
        }
        int inc = sh[tid];
        int total = sh[1023];
        if (i < NNODES) {
            int ex = carry + inc - v;
            g_ptr[i]  = ex;
            g_fill[i] = ex;
        }
        carry += total;
        __syncthreads();
    }
    if (tid == 0) g_ptr[NNODES] = carry;
}

__global__ void k_scatter(const int* __restrict__ coli) {
    int e = blockIdx.x * blockDim.x + threadIdx.x;
    if (e < NEDGES) {
        int pos = atomicAdd(&g_fill[coli[e]], 1);
        g_eid[pos] = e;
    }
}

// ---------------- segment sum ----------------
__global__ void k_segsum(int src_sel, int dst_sel) {
    const float* h = hbuf(src_sel);
    float* dst = dst_sel ? g_s : g_a;
    int t = blockIdx.x * blockDim.x + threadIdx.x;
    if (t >= NNODES * 75) return;
    int n = t / 75;
    int c = (t - n * 75) * 4;
    int beg = g_ptr[n], end = g_ptr[n + 1];
    float4 acc = make_float4(0.f, 0.f, 0.f, 0.f);
#pragma unroll 2
    for (int i = beg; i < end; ++i) {
        int e = g_eid[i];
        float4 vv = ld4(h + e * HIDN + c);
        acc.x += vv.x; acc.y += vv.y; acc.z += vv.z; acc.w += vv.w;
    }
    st4(dst + n * HIDN + c, acc);
}

// ---------- h materialize (bf16 hi/lo): h = relu(h0 + bc + u[row] - rev(t)) --
__global__ void k_hmat(int t_sel, const float* __restrict__ bc,
                       const int* __restrict__ rowi) {
    int t = blockIdx.x * blockDim.x + threadIdx.x;
    if (t >= NEDGES * 80) return;
    int e = t / 80;
    int c = (t - e * 80) * 4;
    float4 v = make_float4(0.f, 0.f, 0.f, 0.f);
    if (c < HIDN) {
        const float* tp = hbuf(t_sel);
        float4 h0v = ld4(g_h0 + e * HIDN + c);
        float4 uv  = ld4(g_a + rowi[e] * HIDN + c);
        float4 tv  = ld4(tp + (e ^ 1) * HIDN + c);
        float4 bv  = ld4(bc + c);
        v.x = frelu(h0v.x + bv.x + uv.x - tv.x);
        v.y = frelu(h0v.y + bv.y + uv.y - tv.y);
        v.z = frelu(h0v.z + bv.z + uv.z - tv.z);
        v.w = frelu(h0v.w + bv.w + uv.w - tv.w);
    }
    uint32_t h0w, l0w, h1w, l1w;
    split_pack(v.x, v.y, h0w, l0w);
    split_pack(v.z, v.w, h1w, l1w);
    *reinterpret_cast<uint2*>(g_Ah + e * 320 + c) = make_uint2(h0w, h1w);
    *reinterpret_cast<uint2*>(g_Al + e * 320 + c) = make_uint2(l0w, l1w);
}

// ---------- h3 materialize fp32: out = relu(h0 + bc2 + u2[row] - rev(t2)) ----
__global__ void k_h3(int t_sel, int out_sel, const float* __restrict__ bc2,
                     const int* __restrict__ rowi) {
    int t = blockIdx.x * blockDim.x + threadIdx.x;
    if (t >= NEDGES * 75) return;
    int e = t / 75;
    int c = (t - e * 75) * 4;
    const float* tp = hbuf(t_sel);
    float* outp = hbuf(out_sel);
    float4 h0v = ld4(g_h0 + e * HIDN + c);
    float4 uv  = ld4(g_a + rowi[e] * HIDN + c);
    float4 tv  = ld4(tp + (e ^ 1) * HIDN + c);
    float4 bv  = ld4(bc2 + c);
    st4(outp + e * HIDN + c, make_float4(
        frelu(h0v.x + bv.x + uv.x - tv.x), frelu(h0v.y + bv.y + uv.y - tv.y),
        frelu(h0v.z + bv.z + uv.z - tv.z), frelu(h0v.w + bv.w + uv.w - tv.w)));
}

// =====================================================================
// Pure conv GEMM, 2-stage cp.async pipeline: t_out = A @ W_layer.
// CTA 128m x 128n, 8 warps (4m x 2n), K=320 in 10 chunks of 32 (SW64).
// Stage = A_hi/A_lo/B_hi/B_lo x 8KB = 32KB; 2 stages = 64KB; 2 CTA/SM.
// 3-pass bf16 split, fp32 acc.
// =====================================================================
#define CG_AH 0
#define CG_AL 8192
#define CG_BH 16384
#define CG_BL 24576
#define CG_STAGE 32768
#define CG_TOTAL 65536

__global__ void __launch_bounds__(256, 2) k_cgemm(int layer, int out_sel) {
    extern __shared__ char smem[];
    uint32_t sb = smem_u32(smem);
    int tid = threadIdx.x;
    int lane = tid & 31;
    int wid = tid >> 5;
    int m0 = blockIdx.y * 128;
    int n0 = blockIdx.x * 128;

    const __nv_bfloat16* Wh = g_Wh + layer * 122880;
    const __nv_bfloat16* Wl = g_Wl + layer * 122880;
    float* tout = hbuf(out_sel);

    int wm = wid >> 1, wn = wid & 1;
    int mat = lane >> 3, l7 = lane & 7;
    int a_row = wm * 32 + (mat & 1) * 8 + l7;
    int a_kof = (mat >> 1) * 8;
    int b_base = wn * 64 + (mat >> 1) * 8 + l7;
    int b_kof = (mat & 1) * 8;
    bool nact = (n0 + wn * 64) < HIDN;

    // per-thread load coords: 512 x 16B per 8KB buffer -> 2 iters of 256
    int lrow = tid >> 2;          // 0..63  (x2 halves)
    int li   = tid & 3;           // 16B slot in 64B row

    float acc[2][8][4];
#pragma unroll
    for (int i = 0; i < 2; i++)
#pragma unroll
        for (int j = 0; j < 8; j++)
#pragma unroll
            for (int q = 0; q < 4; q++) acc[i][j][q] = 0.f;

#define CG_LOAD(KC, ST)                                                        \
    {                                                                          \
        int k0 = (KC) * 32;                                                    \
        uint32_t st = sb + (ST) * CG_STAGE;                                    \
        _Pragma("unroll")                                                      \
        for (int s = 0; s < 2; s++) {                                          \
            int row = lrow + s * 64;                                           \
            uint32_t off = sw64((uint32_t)(row * 64 + li * 16));               \
            const __nv_bfloat16* ah = g_Ah + (size_t)(m0 + row) * 320 + k0 + li * 8; \
            const __nv_bfloat16* al = g_Al + (size_t)(m0 + row) * 320 + k0 + li * 8; \
            CPA16(st + CG_AH + off, ah);                                       \
            CPA16(st + CG_AL + off, al);                                       \
            CPA16(st + CG_BH + off, Wh + (size_t)(n0 + row) * 320 + k0 + li * 8); \
            CPA16(st + CG_BL + off, Wl + (size_t)(n0 + row) * 320 + k0 + li * 8); \
        }                                                                      \
    }

    CG_LOAD(0, 0) CPA_COMMIT();
    CG_LOAD(1, 1) CPA_COMMIT();

    for (int kc = 0; kc < 10; ++kc) {
        if (kc < 9) { CPA_WAIT1(); } else { CPA_WAIT0(); }
        __syncthreads();
        uint32_t st = sb + (kc & 1) * CG_STAGE;
#pragma unroll
        for (int ks = 0; ks < 2; ++ks) {
            uint32_t ah[2][4], al[2][4];
#pragma unroll
            for (int mt = 0; mt < 2; ++mt) {
                uint32_t off = sw64((uint32_t)(((a_row + mt * 16) << 6) +
                                               ((ks * 16 + a_kof) << 1)));
                ldsm4(ah[mt], st + CG_AH + off);
                ldsm4(al[mt], st + CG_AL + off);
            }
            if (nact) {
#pragma unroll
                for (int np = 0; np < 4; ++np) {
                    uint32_t boff = sw64((uint32_t)(((b_base + np * 16) << 6) +
                                                    ((ks * 16 + b_kof) << 1)));
                    uint32_t bh[4], bl[4];
                    ldsm4(bh, st + CG_BH + boff);
                    ldsm4(bl, st + CG_BL + boff);
#pragma unroll
                    for (int mt = 0; mt < 2; ++mt)
#pragma unroll
                        for (int h = 0; h < 2; ++h) {
                            float* d = acc[mt][np * 2 + h];
                            mma_bf(d, ah[mt], bh + h * 2);
                            mma_bf(d, ah[mt], bl + h * 2);
                            mma_bf(d, al[mt], bh + h * 2);
                        }
                }
            }
        }
        __syncthreads();
        if (kc + 2 < 10) { CG_LOAD(kc + 2, kc & 1) CPA_COMMIT(); }
    }
#undef CG_LOAD

    // epilogue: t fp32
    int orow = m0 + wm * 32 + (lane >> 2);
    int oc0  = n0 + wn * 64 + (lane & 3) * 2;
#pragma unroll
    for (int mt = 0; mt < 2; ++mt)
#pragma unroll
        for (int nt = 0; nt < 8; ++nt) {
            int col = oc0 + nt * 8;
            if (col >= HIDN) continue;
#pragma unroll
            for (int h = 0; h < 2; ++h) {
                int row = orow + mt * 16 + h * 8;
                *reinterpret_cast<float2*>(tout + row * HIDN + col) =
                    make_float2(acc[mt][nt][h * 2], acc[mt][nt][h * 2 + 1]);
            }
        }
}

// =====================================================================
// Init GEMM (mma.sync, fly-assembled A = [x[row]|ea], K=80 -> 2 chunks of 64)
// Epilogue: h0 = relu(acc + bias) -> g_h0 fp32 AND g_Ah/g_Al bf16 split.
// =====================================================================
#define TG_A_HI 0
#define TG_A_LO 16384
#define TG_B_HI 32768
#define TG_B_LO 49152
#define TG_TOTAL 65536

__global__ void __launch_bounds__(256, 2) k_tginit(
    const int* __restrict__ rowi, const float* __restrict__ bvec,
    const float* __restrict__ x, const float* __restrict__ ea)
{
    extern __shared__ char smem[];
    uint32_t sb = smem_u32(smem);
    int tid = threadIdx.x;
    int lane = tid & 31;
    int wid = tid >> 5;
    int m0 = blockIdx.y * 128;
    int n0 = blockIdx.x * 128;

    int r = tid >> 1;
    int e = m0 + r;
    int cc0 = (tid & 1) * 32;
    int rv = rowi[e];

    int wm = wid >> 1, wn = wid & 1;
    int mat = lane >> 3, l7 = lane & 7;
    int a_row = wm * 32 + (mat & 1) * 8 + l7;
    int a_kof = (mat >> 1) * 8;
    int b_base = wn * 64 + (mat >> 1) * 8 + l7;
    int b_kof = (mat & 1) * 8;
    bool nact = (n0 + wn * 64) < HIDN;

    float acc[2][8][4];
#pragma unroll
    for (int i = 0; i < 2; i++)
#pragma unroll
        for (int j = 0; j < 8; j++)
#pragma unroll
            for (int q = 0; q < 4; q++) acc[i][j][q] = 0.f;

    for (int kc = 0; kc < 2; ++kc) {
        int k0 = kc * 64;
        if (kc) __syncthreads();
#pragma unroll
        for (int s = 0; s < 4; s++) {
            int j = tid + s * 256;
            int n = j >> 3, i = j & 7;
            uint32_t off = sw128((uint32_t)(n * 128 + i * 16));
            CPA16(sb + TG_B_HI + off, g_WIh + (n0 + n) * 320 + k0 + i * 8);
            CPA16(sb + TG_B_LO + off, g_WIl + (n0 + n) * 320 + k0 + i * 8);
        }
        CPA_COMMIT();
#pragma unroll
        for (int i = 0; i < 8; i++) {
            int cc = cc0 + i * 4;
            int k = k0 + cc;
            float4 v = make_float4(0.f, 0.f, 0.f, 0.f);
            if (k < FNODE)    v = ld4(x + rv * FNODE + k);
            else if (k < 80)  v = ld4(ea + e * FEDGE + (k - FNODE));
            uint32_t h0w, l0w, h1w, l1w;
            split_pack(v.x, v.y, h0w, l0w);
            split_pack(v.z, v.w, h1w, l1w);
            uint32_t off = sw128((uint32_t)(r * 128 + cc * 2));
            *reinterpret_cast<uint2*>(smem + TG_A_HI + off) = make_uint2(h0w, h1w);
            *reinterpret_cast<uint2*>(smem + TG_A_LO + off) = make_uint2(l0w, l1w);
        }
        CPA_WAIT0();
        __syncthreads();
#pragma unroll
        for (int ks = 0; ks < 4; ++ks) {
            uint32_t ah[2][4], al[2][4];
#pragma unroll
            for (int mt = 0; mt < 2; ++mt) {
                uint32_t off = sw128((uint32_t)(((a_row + mt * 16) << 7) +
                                                ((ks * 16 + a_kof) << 1)));
                ldsm4(ah[mt], sb + TG_A_HI + off);
                ldsm4(al[mt], sb + TG_A_LO + off);
            }
            if (nact) {
#pragma unroll
                for (int np = 0; np < 4; ++np) {
                    uint32_t boff = sw128((uint32_t)(((b_base + np * 16) << 7) +
                                                     ((ks * 16 + b_kof) << 1)));
                    uint32_t bh[4], bl[4];
                    ldsm4(bh, sb + TG_B_HI + boff);
                    ldsm4(bl, sb + TG_B_LO + boff);
#pragma unroll
                    for (int mt = 0; mt < 2; ++mt)
#pragma unroll
                        for (int h = 0; h < 2; ++h) {
                            float* d = acc[mt][np * 2 + h];
                            mma_bf(d, ah[mt], bh + h * 2);
                            mma_bf(d, ah[mt], bl + h * 2);
                            mma_bf(d, al[mt], bh + h * 2);
                        }
                }
            }
        }
    }

    // epilogue: h0 fp32 + bf16 split
    int orow = m0 + wm * 32 + (lane >> 2);
    int oc0  = n0 + wn * 64 + (lane & 3) * 2;
#pragma unroll
    for (int mt = 0; mt < 2; ++mt)
#pragma unroll
        for (int nt = 0; nt < 8; ++nt) {
            int col = oc0 + nt * 8;
            if (col >= 320) continue;
            bool live = col < HIDN;
            float b0 = live ? bvec[col] : 0.f;
            float b1 = live ? bvec[col + 1] : 0.f;
#pragma unroll
            for (int h = 0; h < 2; ++h) {
                int row = orow + mt * 16 + h * 8;
                float v0 = live ? frelu(acc[mt][nt][h * 2] + b0) : 0.f;
                float v1 = live ? frelu(acc[mt][nt][h * 2 + 1] + b1) : 0.f;
                if (live)
                    *reinterpret_cast<float2*>(g_h0 + row * HIDN + col) = make_float2(v0, v1);
                uint32_t hw, lw;
                split_pack(v0, v1, hw, lw);
                *reinterpret_cast<uint32_t*>(g_Ah + (size_t)row * 320 + col) = hw;
                *reinterpret_cast<uint32_t*>(g_Al + (size_t)row * 320 + col) = lw;
            }
        }
}

// =====================================================================
// FFMA2 GEMM (k_node): 128x64 tile, 8x8/thread
// =====================================================================
#define GEMM_DECLS                                                         \
    __shared__ __align__(16) float As[20 * 256];                           \
    __shared__ __align__(16) float Bs[20 * 64];                            \
    float2* As2 = reinterpret_cast<float2*>(As);                           \
    int tid = threadIdx.x;                                                 \
    int ty = tid >> 3, tx = tid & 7;                                       \
    ull acc[8][4];                                                         \
    _Pragma("unroll")                                                      \
    for (int i = 0; i < 8; i++)                                            \
        _Pragma("unroll")                                                  \
        for (int j = 0; j < 4; j++) acc[i][j] = 0ull;                      \
    float4 pa[5], pb[3];

#define GEMM_STORE_STAGE                                                   \
    _Pragma("unroll")                                                      \
    for (int v = 0; v < 5; v++) {                                          \
        float4 w = pa[v];                                                  \
        As2[(v * 4 + 0) * 128 + tid] = make_float2(w.x, w.x);              \
        As2[(v * 4 + 1) * 128 + tid] = make_float2(w.y, w.y);              \
        As2[(v * 4 + 2) * 128 + tid] = make_float2(w.z, w.z);              \
        As2[(v * 4 + 3) * 128 + tid] = make_float2(w.w, w.w);              \
    }                                                                      \
    _Pragma("unroll")                                                      \
    for (int s = 0; s < 3; s++) {                                          \
        int j = tid + s * 128;                                             \
        if (j < 320) {                                                     \
            int kk = j >> 4, nv = j & 15;                                  \
            st4(&Bs[kk * 64 + nv * 4], pb[s]);                             \
        }                                                                  \
    }

#define GEMM_COMPUTE_STAGE                                                 \
    _Pragma("unroll")                                                      \
    for (int kk = 0; kk < 20; kk++) {                                      \
        const ulonglong2* Ap =                                             \
            reinterpret_cast<const ulonglong2*>(&As[kk * 256 + ty * 16]);  \
        const ulonglong2* Bp =                                             \
            reinterpret_cast<const ulonglong2*>(&Bs[kk * 64 + tx * 8]);    \
        ulonglong2 A0 = Ap[0], A1 = Ap[1], A2 = Ap[2], A3 = Ap[3];         \
        ulonglong2 B0 = Bp[0], B1 = Bp[1];                                 \
        ull a2[8] = {A0.x, A0.y, A1.x, A1.y, A2.x, A2.y, A3.x, A3.y};      \
        ull b2[4] = {B0.x, B0.y, B1.x, B1.y};                              \
        _Pragma("unroll")                                                  \
        for (int i = 0; i < 8; i++)                                        \
            _Pragma("unroll")                                              \
            for (int j = 0; j < 4; j++)                                    \
                acc[i][j] = fma2(a2[i], b2[j], acc[i][j]);                 \
    }

__global__ __launch_bounds__(128, 3) void k_node(
    const float* __restrict__ x, const int* __restrict__ batch,
    const float* __restrict__ W, const float* __restrict__ bias)
{
    GEMM_DECLS
    int m0 = blockIdx.y * 128;
    int n0 = blockIdx.x * 64;
    int eg = m0 + tid;
    bool mok = (eg < NNODES);
    int safe = mok ? eg : 0;
    int xbase = safe * FNODE;
    int sbase = safe * HIDN;
    const int KTOT = FNODE + HIDN;  // 364
    const int NK = 19;

#define LOAD_STAGE(K0)                                                     \
    {                                                                      \
        int k0 = (K0);                                                     \
        _Pragma("unroll")                                                  \
        for (int v = 0; v < 5; v++) {                                      \
            int k = k0 + v * 4;                                            \
            if (k < KTOT)                                                  \
                pa[v] = (k < FNODE) ? ld4(x + xbase + k)                   \
                                    : ld4(g_s + sbase + (k - FNODE));      \
            else                                                           \
                pa[v] = make_float4(0.f, 0.f, 0.f, 0.f);                   \
        }                                                                  \
        _Pragma("unroll")                                                  \
        for (int s = 0; s < 3; s++) {                                      \
            int j = tid + s * 128;                                         \
            if (j < 320) {                                                 \
                int kk = j >> 4, nv = j & 15;                              \
                int k = k0 + kk;                                           \
                int n = n0 + nv * 4;                                       \
                pb[s] = (k < KTOT && n < HIDN)                             \
                            ? ld4(W + k * HIDN + n)                        \
                            : make_float4(0.f, 0.f, 0.f, 0.f);             \
            }                                                              \
        }                                                                  \
    }

    LOAD_STAGE(0)
    for (int ks = 0; ks < NK; ++ks) {
        __syncthreads();
        GEMM_STORE_STAGE
        __syncthreads();
        if (ks + 1 < NK) LOAD_STAGE((ks + 1) * 20)
        GEMM_COMPUTE_STAGE
    }
    int nb = n0 + tx * 8;
    float4 bias0 = (nb < HIDN) ? ld4(bias + nb) : make_float4(0, 0, 0, 0);
    float4 bias1 = (nb + 4 < HIDN) ? ld4(bias + nb + 4) : make_float4(0, 0, 0, 0);
#pragma unroll
    for (int i = 0; i < 8; i++) {
        int m = m0 + ty * 8 + i;
        if (m >= NNODES) continue;
        float c0, c1, c2, c3, c4, c5, c6, c7;
        unpack2(acc[i][0], c0, c1); unpack2(acc[i][1], c2, c3);
        unpack2(acc[i][2], c4, c5); unpack2(acc[i][3], c6, c7);
        int bg = batch[m];
        float* p = g_pool + bg * HIDN;
        if (nb < HIDN) {
            atomicAdd(p + nb + 0, frelu(c0 + bias0.x));
            atomicAdd(p + nb + 1, frelu(c1 + bias0.y));
            atomicAdd(p + nb + 2, frelu(c2 + bias0.z));
            atomicAdd(p + nb + 3, frelu(c3 + bias0.w));
        }
        if (nb + 4 < HIDN) {
            atomicAdd(p + nb + 4, frelu(c4 + bias1.x));
            atomicAdd(p + nb + 5, frelu(c5 + bias1.y));
            atomicAdd(p + nb + 6, frelu(c6 + bias1.z));
            atomicAdd(p + nb + 7, frelu(c7 + bias1.w));
        }
    }
#undef LOAD_STAGE
}

// ---------------- FFN ----------------
__global__ void k_ffn(const float* __restrict__ Wf, const float* __restrict__ bf,
                      float* __restrict__ out) {
    int g = blockIdx.x;
    int lane = threadIdx.x;
    float s = 0.f;
    for (int k = lane; k < HIDN; k += 32) s += g_pool[g * HIDN + k] * Wf[k];
#pragma unroll
    for (int o = 16; o; o >>= 1) s += __shfl_xor_sync(0xffffffffu, s, o);
    if (lane == 0) out[g] = s + bf[0];
}

// ---------------- entry ----------------
extern "C" void kernel_launch(void* const* d_in, const int* in_sizes, int n_in,
                              void* d_out, int out_size) {
    const float* x     = (const float*)d_in[0];
    const float* ea    = (const float*)d_in[1];
    const int*   ei    = (const int*)d_in[2];
    const int*   rowi  = ei;
    const int*   coli  = ei + NEDGES;
    const int*   batch = (const int*)d_in[3];
    const float* Wi    = (const float*)d_in[4];
    const float* bi    = (const float*)d_in[5];
    const float* Wc    = (const float*)d_in[6];
    const float* bc    = (const float*)d_in[7];
    const float* We    = (const float*)d_in[8];
    const float* be    = (const float*)d_in[9];
    const float* Wf    = (const float*)d_in[10];
    const float* bf    = (const float*)d_in[11];
    float* out = (float*)d_out;

    cudaFuncSetAttribute(k_cgemm, cudaFuncAttributeMaxDynamicSharedMemorySize, CG_TOTAL);
    cudaFuncSetAttribute(k_tginit, cudaFuncAttributeMaxDynamicSharedMemorySize, TG_TOTAL);

    dim3 gT(3, NEDGES / 128);
    int ssB  = (NNODES * 75 + 255) / 256;
    int hmB  = (NEDGES * 80) / 256;
    int h3B  = (NEDGES * 75 + 255) / 256;

    k_pre<<<1440, 256>>>(Wc, Wi);                       // 1
    k_hist<<<NEDGES / 256, 256>>>(coli);                // 2
    k_tginit<<<gT, 256, TG_TOTAL>>>(rowi, bi, x, ea);   // 3: h0 + A bf16
    k_cgemm<<<gT, 256, CG_TOTAL>>>(0, 1);               // 4: t0  <- profiled
    k_scan<<<1, 1024>>>();                              // 5
    k_scatter<<<NEDGES / 256, 256>>>(coli);             // 6

    k_segsum<<<ssB, 256>>>(1, 0);                       // u0
    k_hmat<<<hmB, 256>>>(1, bc, rowi);                  // A = h1 bf16
    k_cgemm<<<gT, 256, CG_TOTAL>>>(1, 2);               // t1
    k_segsum<<<ssB, 256>>>(2, 0);                       // u1
    k_hmat<<<hmB, 256>>>(2, bc + HIDN, rowi);           // A = h2 bf16
    k_cgemm<<<gT, 256, CG_TOTAL>>>(2, 1);               // t2
    k_segsum<<<ssB, 256>>>(1, 0);                       // u2
    k_h3<<<h3B, 256>>>(1, 2, bc + 2 * HIDN, rowi);      // h3 fp32 -> g_hB
    k_segsum<<<ssB, 256>>>(2, 1);                       // s -> g_s

    dim3 gN(5, (NNODES + 127) / 128);
    k_node<<<gN, 128>>>(x, batch, We, be);
    k_ffn<<<NGRAPH, 32>>>(Wf, bf, out);
}

// round 8
// speedup vs baseline: 1.1067x; 1.1067x over previous
#include <cuda_runtime.h>
#include <cuda_bf16.h>
#include <cstdint>

#define NNODES 20000
#define NEDGES 320000
#define FNODE  64
#define FEDGE  16
#define HIDN   300
#define NGRAPH 128

typedef unsigned long long ull;

// ---------------- scratch (device globals) ----------------
__device__ float g_h0[NEDGES * HIDN];
__device__ float g_hA[NEDGES * HIDN];          // t ping
__device__ float g_hB[NEDGES * HIDN];          // t pong
__device__ __nv_bfloat16 g_Ah[NEDGES * 320];   // A operand hi (current layer)
__device__ __nv_bfloat16 g_Al[NEDGES * 320];   // A operand lo
__device__ float g_a [NNODES * HIDN];          // u = segsum(t)
__device__ float g_s [NNODES * HIDN];          // final node message
__device__ float g_pool[NGRAPH * HIDN];
__device__ __nv_bfloat16 g_Wh [3 * 384 * 320]; // conv W^T hi [l][n][k], zero-pad
__device__ __nv_bfloat16 g_Wl [3 * 384 * 320];
__device__ __nv_bfloat16 g_WIh[384 * 320];     // init W^T hi
__device__ __nv_bfloat16 g_WIl[384 * 320];
__device__ __nv_bfloat16 g_WNh[384 * 384];     // e2n W^T hi [n][k]
__device__ __nv_bfloat16 g_WNl[384 * 384];
__device__ int g_cnt [NNODES];
__device__ int g_ptr [NNODES + 1];
__device__ int g_fill[NNODES];
__device__ int g_eid [NEDGES];

__device__ __forceinline__ float* hbuf(int s) {
    return (s == 0) ? g_h0 : ((s == 1) ? g_hA : g_hB);
}

// ---------------- helpers ----------------
__device__ __forceinline__ float4 ld4(const float* p) { return *reinterpret_cast<const float4*>(p); }
__device__ __forceinline__ void   st4(float* p, float4 v) { *reinterpret_cast<float4*>(p) = v; }
__device__ __forceinline__ float  frelu(float x) { return x > 0.f ? x : 0.f; }

__device__ __forceinline__ uint32_t smem_u32(const void* p) {
    uint32_t a;
    asm("{ .reg .u64 t; cvta.to.shared.u64 t, %1; cvt.u32.u64 %0, t; }" : "=r"(a) : "l"(p));
    return a;
}
__device__ __forceinline__ uint32_t sw128(uint32_t o) { return o ^ ((o >> 3) & 0x70); }

__device__ __forceinline__ void ldsm4(uint32_t* r, uint32_t a) {
    asm volatile("ldmatrix.sync.aligned.m8n8.x4.shared.b16 {%0,%1,%2,%3}, [%4];"
                 : "=r"(r[0]), "=r"(r[1]), "=r"(r[2]), "=r"(r[3]) : "r"(a));
}
__device__ __forceinline__ void mma_bf(float* d, const uint32_t* a, const uint32_t* b) {
    asm volatile("mma.sync.aligned.m16n8k16.row.col.f32.bf16.bf16.f32 "
                 "{%0,%1,%2,%3}, {%4,%5,%6,%7}, {%8,%9}, {%0,%1,%2,%3};"
                 : "+f"(d[0]), "+f"(d[1]), "+f"(d[2]), "+f"(d[3])
                 : "r"(a[0]), "r"(a[1]), "r"(a[2]), "r"(a[3]), "r"(b[0]), "r"(b[1]));
}
#define CPA16(dst, src) asm volatile("cp.async.cg.shared.global [%0], [%1], 16;" :: "r"(dst), "l"(src))
#define CPA_COMMIT()    asm volatile("cp.async.commit_group;" ::: "memory")
#define CPA_WAIT0()     asm volatile("cp.async.wait_group 0;" ::: "memory")

__device__ __forceinline__ void split_pack(float v0, float v1, uint32_t& hi, uint32_t& lo) {
    __nv_bfloat162 h, l;
    h.x = __float2bfloat16(v0); h.y = __float2bfloat16(v1);
    l.x = __float2bfloat16(v0 - __bfloat162float(h.x));
    l.y = __float2bfloat16(v1 - __bfloat162float(h.y));
    hi = *reinterpret_cast<uint32_t*>(&h);
    lo = *reinterpret_cast<uint32_t*>(&l);
}

// ---------------- preprocessing ----------------
__global__ void k_pre(const float* __restrict__ Wc, const float* __restrict__ Wi,
                      const float* __restrict__ We) {
    int t = blockIdx.x * blockDim.x + threadIdx.x;
    if (t < NNODES) g_cnt[t] = 0;
    if (t < NGRAPH * HIDN) g_pool[t] = 0.f;
    if (t < 122880) {
        int n = t / 320, k = t % 320;
        float v = (n < HIDN && k < 80) ? Wi[k * HIDN + n] : 0.f;
        __nv_bfloat16 bh = __float2bfloat16(v);
        g_WIh[t] = bh;
        g_WIl[t] = __float2bfloat16(v - __bfloat162float(bh));
    }
    if (t < 3 * 122880) {
        int l = t / 122880, r2 = t % 122880;
        int n = r2 / 320, k = r2 % 320;
        float v = (n < HIDN && k < HIDN) ? Wc[l * HIDN * HIDN + k * HIDN + n] : 0.f;
        __nv_bfloat16 bh = __float2bfloat16(v);
        g_Wh[t] = bh;
        g_Wl[t] = __float2bfloat16(v - __bfloat162float(bh));
    }
    if (t < 384 * 384) {
        int n = t / 384, k = t % 384;
        float v = (n < HIDN && k < FNODE + HIDN) ? We[k * HIDN + n] : 0.f;
        __nv_bfloat16 bh = __float2bfloat16(v);
        g_WNh[t] = bh;
        g_WNl[t] = __float2bfloat16(v - __bfloat162float(bh));
    }
}

__global__ void k_hist(const int* __restrict__ coli) {
    int e = blockIdx.x * blockDim.x + threadIdx.x;
    if (e < NEDGES) atomicAdd(&g_cnt[coli[e]], 1);
}

__global__ void k_scan() {
    __shared__ int sh[1024];
    int tid = threadIdx.x;
    int carry = 0;
    const int CH = (NNODES + 1023) / 1024;
    for (int c = 0; c < CH; ++c) {
        int i = c * 1024 + tid;
        int v = (i < NNODES) ? g_cnt[i] : 0;
        sh[tid] = v;
        __syncthreads();
        for (int off = 1; off < 1024; off <<= 1) {
            int t = (tid >= off) ? sh[tid - off] : 0;
            __syncthreads();
            sh[tid] += t;
            __syncthreads();
        }
        int inc = sh[tid];
        int total = sh[1023];
        if (i < NNODES) {
            int ex = carry + inc - v;
            g_ptr[i]  = ex;
            g_fill[i] = ex;
        }
        carry += total;
        __syncthreads();
    }
    if (tid == 0) g_ptr[NNODES] = carry;
}

__global__ void k_scatter(const int* __restrict__ coli) {
    int e = blockIdx.x * blockDim.x + threadIdx.x;
    if (e < NEDGES) {
        int pos = atomicAdd(&g_fill[coli[e]], 1);
        g_eid[pos] = e;
    }
}

// ---------------- segment sum: g_a[n] = sum t[e] ----------------
__global__ void k_segsum(int src_sel) {
    const float* h = hbuf(src_sel);
    int t = blockIdx.x * blockDim.x + threadIdx.x;
    if (t >= NNODES * 75) return;
    int n = t / 75;
    int c = (t - n * 75) * 4;
    int beg = g_ptr[n], end = g_ptr[n + 1];
    float4 acc = make_float4(0.f, 0.f, 0.f, 0.f);
#pragma unroll 2
    for (int i = beg; i < end; ++i) {
        int e = g_eid[i];
        float4 vv = ld4(h + e * HIDN + c);
        acc.x += vv.x; acc.y += vv.y; acc.z += vv.z; acc.w += vv.w;
    }
    st4(g_a + n * HIDN + c, acc);
}

// --------- fused final: g_s[n] = sum_e relu(h0[e]+bc2+u2[row[e]]-rev(t2)) ----
__global__ void k_segsum_h3(int t2_sel, const float* __restrict__ bc2,
                            const int* __restrict__ rowi) {
    const float* t2 = hbuf(t2_sel);
    int t = blockIdx.x * blockDim.x + threadIdx.x;
    if (t >= NNODES * 75) return;
    int n = t / 75;
    int c = (t - n * 75) * 4;
    float4 bv = ld4(bc2 + c);
    int beg = g_ptr[n], end = g_ptr[n + 1];
    float4 acc = make_float4(0.f, 0.f, 0.f, 0.f);
#pragma unroll 2
    for (int i = beg; i < end; ++i) {
        int e = g_eid[i];
        float4 h0v = ld4(g_h0 + e * HIDN + c);
        float4 uv  = ld4(g_a + rowi[e] * HIDN + c);
        float4 tv  = ld4(t2 + (e ^ 1) * HIDN + c);
        acc.x += frelu(h0v.x + bv.x + uv.x - tv.x);
        acc.y += frelu(h0v.y + bv.y + uv.y - tv.y);
        acc.z += frelu(h0v.z + bv.z + uv.z - tv.z);
        acc.w += frelu(h0v.w + bv.w + uv.w - tv.w);
    }
    st4(g_s + n * HIDN + c, acc);
}

// ---------- h materialize (bf16 hi/lo): h = relu(h0 + bc + u[row] - rev(t)) --
__global__ void k_hmat(int t_sel, const float* __restrict__ bc,
                       const int* __restrict__ rowi) {
    int t = blockIdx.x * blockDim.x + threadIdx.x;
    if (t >= NEDGES * 80) return;
    int e = t / 80;
    int c = (t - e * 80) * 4;
    float4 v = make_float4(0.f, 0.f, 0.f, 0.f);
    if (c < HIDN) {
        const float* tp = hbuf(t_sel);
        float4 h0v = ld4(g_h0 + e * HIDN + c);
        float4 uv  = ld4(g_a + rowi[e] * HIDN + c);
        float4 tv  = ld4(tp + (e ^ 1) * HIDN + c);
        float4 bv  = ld4(bc + c);
        v.x = frelu(h0v.x + bv.x + uv.x - tv.x);
        v.y = frelu(h0v.y + bv.y + uv.y - tv.y);
        v.z = frelu(h0v.z + bv.z + uv.z - tv.z);
        v.w = frelu(h0v.w + bv.w + uv.w - tv.w);
    }
    uint32_t h0w, l0w, h1w, l1w;
    split_pack(v.x, v.y, h0w, l0w);
    split_pack(v.z, v.w, h1w, l1w);
    *reinterpret_cast<uint2*>(g_Ah + e * 320 + c) = make_uint2(h0w, h1w);
    *reinterpret_cast<uint2*>(g_Al + e * 320 + c) = make_uint2(l0w, l1w);
}

// =====================================================================
// Pure conv GEMM (R6-proven): t_out = A @ W_layer, K=320 in 5 chunks of 64.
// CTA 128m x 128n, 8 warps (4m x 2n), SW128, cp.async, 3-pass bf16 split.
// =====================================================================
#define TG_A_HI 0
#define TG_A_LO 16384
#define TG_B_HI 32768
#define TG_B_LO 49152
#define TG_TOTAL 65536

__global__ void __launch_bounds__(256, 2) k_cgemm(int layer, int out_sel) {
    extern __shared__ char smem[];
    uint32_t sb = smem_u32(smem);
    int tid = threadIdx.x;
    int lane = tid & 31;
    int wid = tid >> 5;
    int m0 = blockIdx.y * 128;
    int n0 = blockIdx.x * 128;

    const __nv_bfloat16* Wh = g_Wh + layer * 122880;
    const __nv_bfloat16* Wl = g_Wl + layer * 122880;
    float* tout = hbuf(out_sel);

    int wm = wid >> 1, wn = wid & 1;
    int mat = lane >> 3, l7 = lane & 7;
    int a_row = wm * 32 + (mat & 1) * 8 + l7;
    int a_kof = (mat >> 1) * 8;
    int b_base = wn * 64 + (mat >> 1) * 8 + l7;
    int b_kof = (mat & 1) * 8;
    bool nact = (n0 + wn * 64) < HIDN;

    float acc[2][8][4];
#pragma unroll
    for (int i = 0; i < 2; i++)
#pragma unroll
        for (int j = 0; j < 8; j++)
#pragma unroll
            for (int q = 0; q < 4; q++) acc[i][j][q] = 0.f;

    for (int kc = 0; kc < 5; ++kc) {
        int k0 = kc * 64;
        if (kc) __syncthreads();
#pragma unroll
        for (int s = 0; s < 4; s++) {
            int j = tid + s * 256;
            int r2 = j >> 3, i = j & 7;
            uint32_t off = sw128((uint32_t)(r2 * 128 + i * 16));
            CPA16(sb + TG_A_HI + off, g_Ah + (size_t)(m0 + r2) * 320 + k0 + i * 8);
            CPA16(sb + TG_A_LO + off, g_Al + (size_t)(m0 + r2) * 320 + k0 + i * 8);
        }
#pragma unroll
        for (int s = 0; s < 4; s++) {
            int j = tid + s * 256;
            int n = j >> 3, i = j & 7;
            uint32_t off = sw128((uint32_t)(n * 128 + i * 16));
            CPA16(sb + TG_B_HI + off, Wh + (n0 + n) * 320 + k0 + i * 8);
            CPA16(sb + TG_B_LO + off, Wl + (n0 + n) * 320 + k0 + i * 8);
        }
        CPA_COMMIT();
        CPA_WAIT0();
        __syncthreads();

#pragma unroll
        for (int ks = 0; ks < 4; ++ks) {
            uint32_t ah[2][4], al[2][4];
#pragma unroll
            for (int mt = 0; mt < 2; ++mt) {
                uint32_t off = sw128((uint32_t)(((a_row + mt * 16) << 7) +
                                                ((ks * 16 + a_kof) << 1)));
                ldsm4(ah[mt], sb + TG_A_HI + off);
                ldsm4(al[mt], sb + TG_A_LO + off);
            }
            if (nact) {
#pragma unroll
                for (int np = 0; np < 4; ++np) {
                    uint32_t boff = sw128((uint32_t)(((b_base + np * 16) << 7) +
                                                     ((ks * 16 + b_kof) << 1)));
                    uint32_t bh[4], bl[4];
                    ldsm4(bh, sb + TG_B_HI + boff);
                    ldsm4(bl, sb + TG_B_LO + boff);
#pragma unroll
                    for (int mt = 0; mt < 2; ++mt)
#pragma unroll
                        for (int h = 0; h < 2; ++h) {
                            float* d = acc[mt][np * 2 + h];
                            mma_bf(d, ah[mt], bh + h * 2);
                            mma_bf(d, ah[mt], bl + h * 2);
                            mma_bf(d, al[mt], bh + h * 2);
                        }
                }
            }
        }
    }

    int orow = m0 + wm * 32 + (lane >> 2);
    int oc0  = n0 + wn * 64 + (lane & 3) * 2;
#pragma unroll
    for (int mt = 0; mt < 2; ++mt)
#pragma unroll
        for (int nt = 0; nt < 8; ++nt) {
            int col = oc0 + nt * 8;
            if (col >= HIDN) continue;
#pragma unroll
            for (int h = 0; h < 2; ++h) {
                int row = orow + mt * 16 + h * 8;
                *reinterpret_cast<float2*>(tout + row * HIDN + col) =
                    make_float2(acc[mt][nt][h * 2], acc[mt][nt][h * 2 + 1]);
            }
        }
}

// =====================================================================
// Init GEMM: A = [x[row]|ea] (K=80 -> 2 chunks), epilogue h0 fp32 + bf16 split
// =====================================================================
__global__ void __launch_bounds__(256, 2) k_tginit(
    const int* __restrict__ rowi, const float* __restrict__ bvec,
    const float* __restrict__ x, const float* __restrict__ ea)
{
    extern __shared__ char smem[];
    uint32_t sb = smem_u32(smem);
    int tid = threadIdx.x;
    int lane = tid & 31;
    int wid = tid >> 5;
    int m0 = blockIdx.y * 128;
    int n0 = blockIdx.x * 128;

    int r = tid >> 1;
    int e = m0 + r;
    int cc0 = (tid & 1) * 32;
    int rv = rowi[e];

    int wm = wid >> 1, wn = wid & 1;
    int mat = lane >> 3, l7 = lane & 7;
    int a_row = wm * 32 + (mat & 1) * 8 + l7;
    int a_kof = (mat >> 1) * 8;
    int b_base = wn * 64 + (mat >> 1) * 8 + l7;
    int b_kof = (mat & 1) * 8;
    bool nact = (n0 + wn * 64) < HIDN;

    float acc[2][8][4];
#pragma unroll
    for (int i = 0; i < 2; i++)
#pragma unroll
        for (int j = 0; j < 8; j++)
#pragma unroll
            for (int q = 0; q < 4; q++) acc[i][j][q] = 0.f;

    for (int kc = 0; kc < 2; ++kc) {
        int k0 = kc * 64;
        if (kc) __syncthreads();
#pragma unroll
        for (int s = 0; s < 4; s++) {
            int j = tid + s * 256;
            int n = j >> 3, i = j & 7;
            uint32_t off = sw128((uint32_t)(n * 128 + i * 16));
            CPA16(sb + TG_B_HI + off, g_WIh + (n0 + n) * 320 + k0 + i * 8);
            CPA16(sb + TG_B_LO + off, g_WIl + (n0 + n) * 320 + k0 + i * 8);
        }
        CPA_COMMIT();
#pragma unroll
        for (int i = 0; i < 8; i++) {
            int cc = cc0 + i * 4;
            int k = k0 + cc;
            float4 v = make_float4(0.f, 0.f, 0.f, 0.f);
            if (k < FNODE)    v = ld4(x + rv * FNODE + k);
            else if (k < 80)  v = ld4(ea + e * FEDGE + (k - FNODE));
            uint32_t h0w, l0w, h1w, l1w;
            split_pack(v.x, v.y, h0w, l0w);
            split_pack(v.z, v.w, h1w, l1w);
            uint32_t off = sw128((uint32_t)(r * 128 + cc * 2));
            *reinterpret_cast<uint2*>(smem + TG_A_HI + off) = make_uint2(h0w, h1w);
            *reinterpret_cast<uint2*>(smem + TG_A_LO + off) = make_uint2(l0w, l1w);
        }
        CPA_WAIT0();
        __syncthreads();
#pragma unroll
        for (int ks = 0; ks < 4; ++ks) {
            uint32_t ah[2][4], al[2][4];
#pragma unroll
            for (int mt = 0; mt < 2; ++mt) {
                uint32_t off = sw128((uint32_t)(((a_row + mt * 16) << 7) +
                                                ((ks * 16 + a_kof) << 1)));
                ldsm4(ah[mt], sb + TG_A_HI + off);
                ldsm4(al[mt], sb + TG_A_LO + off);
            }
            if (nact) {
#pragma unroll
                for (int np = 0; np < 4; ++np) {
                    uint32_t boff = sw128((uint32_t)(((b_base + np * 16) << 7) +
                                                     ((ks * 16 + b_kof) << 1)));
                    uint32_t bh[4], bl[4];
                    ldsm4(bh, sb + TG_B_HI + boff);
                    ldsm4(bl, sb + TG_B_LO + boff);
#pragma unroll
                    for (int mt = 0; mt < 2; ++mt)
#pragma unroll
                        for (int h = 0; h < 2; ++h) {
                            float* d = acc[mt][np * 2 + h];
                            mma_bf(d, ah[mt], bh + h * 2);
                            mma_bf(d, ah[mt], bl + h * 2);
                            mma_bf(d, al[mt], bh + h * 2);
                        }
                }
            }
        }
    }

    int orow = m0 + wm * 32 + (lane >> 2);
    int oc0  = n0 + wn * 64 + (lane & 3) * 2;
#pragma unroll
    for (int mt = 0; mt < 2; ++mt)
#pragma unroll
        for (int nt = 0; nt < 8; ++nt) {
            int col = oc0 + nt * 8;
            if (col >= 320) continue;
            bool live = col < HIDN;
            float b0 = live ? bvec[col] : 0.f;
            float b1 = live ? bvec[col + 1] : 0.f;
#pragma unroll
            for (int h = 0; h < 2; ++h) {
                int row = orow + mt * 16 + h * 8;
                float v0 = live ? frelu(acc[mt][nt][h * 2] + b0) : 0.f;
                float v1 = live ? frelu(acc[mt][nt][h * 2 + 1] + b1) : 0.f;
                if (live)
                    *reinterpret_cast<float2*>(g_h0 + row * HIDN + col) = make_float2(v0, v1);
                uint32_t hw, lw;
                split_pack(v0, v1, hw, lw);
                *reinterpret_cast<uint32_t*>(g_Ah + (size_t)row * 320 + col) = hw;
                *reinterpret_cast<uint32_t*>(g_Al + (size_t)row * 320 + col) = lw;
            }
        }
}

// =====================================================================
// Node GEMM (tensor): hn = relu([x|s] @ W_e2n + be); pool += hn
// A assembled on the fly, K=364 -> 6 chunks of 64 (pad 384).
// =====================================================================
__global__ void __launch_bounds__(256, 2) k_tgnode(
    const int* __restrict__ batch, const float* __restrict__ bvec,
    const float* __restrict__ x)
{
    extern __shared__ char smem[];
    uint32_t sb = smem_u32(smem);
    int tid = threadIdx.x;
    int lane = tid & 31;
    int wid = tid >> 5;
    int m0 = blockIdx.y * 128;
    int n0 = blockIdx.x * 128;

    int r = tid >> 1;
    int e = m0 + r;
    bool eok = (e < NNODES);
    int es = eok ? e : 0;
    int cc0 = (tid & 1) * 32;

    int wm = wid >> 1, wn = wid & 1;
    int mat = lane >> 3, l7 = lane & 7;
    int a_row = wm * 32 + (mat & 1) * 8 + l7;
    int a_kof = (mat >> 1) * 8;
    int b_base = wn * 64 + (mat >> 1) * 8 + l7;
    int b_kof = (mat & 1) * 8;
    bool nact = (n0 + wn * 64) < HIDN;

    const int KTOT = FNODE + HIDN;  // 364

    float acc[2][8][4];
#pragma unroll
    for (int i = 0; i < 2; i++)
#pragma unroll
        for (int j = 0; j < 8; j++)
#pragma unroll
            for (int q = 0; q < 4; q++) acc[i][j][q] = 0.f;

    for (int kc = 0; kc < 6; ++kc) {
        int k0 = kc * 64;
        if (kc) __syncthreads();
#pragma unroll
        for (int s = 0; s < 4; s++) {
            int j = tid + s * 256;
            int n = j >> 3, i = j & 7;
            uint32_t off = sw128((uint32_t)(n * 128 + i * 16));
            CPA16(sb + TG_B_HI + off, g_WNh + (n0 + n) * 384 + k0 + i * 8);
            CPA16(sb + TG_B_LO + off, g_WNl + (n0 + n) * 384 + k0 + i * 8);
        }
        CPA_COMMIT();
#pragma unroll
        for (int i = 0; i < 8; i++) {
            int cc = cc0 + i * 4;
            int k = k0 + cc;
            float4 v = make_float4(0.f, 0.f, 0.f, 0.f);
            if (eok && k < KTOT)
                v = (k < FNODE) ? ld4(x + es * FNODE + k)
                                : ld4(g_s + es * HIDN + (k - FNODE));
            uint32_t h0w, l0w, h1w, l1w;
            split_pack(v.x, v.y, h0w, l0w);
            split_pack(v.z, v.w, h1w, l1w);
            uint32_t off = sw128((uint32_t)(r * 128 + cc * 2));
            *reinterpret_cast<uint2*>(smem + TG_A_HI + off) = make_uint2(h0w, h1w);
            *reinterpret_cast<uint2*>(smem + TG_A_LO + off) = make_uint2(l0w, l1w);
        }
        CPA_WAIT0();
        __syncthreads();
#pragma unroll
        for (int ks = 0; ks < 4; ++ks) {
            uint32_t ah[2][4], al[2][4];
#pragma unroll
            for (int mt = 0; mt < 2; ++mt) {
                uint32_t off = sw128((uint32_t)(((a_row + mt * 16) << 7) +
                                                ((ks * 16 + a_kof) << 1)));
                ldsm4(ah[mt], sb + TG_A_HI + off);
                ldsm4(al[mt], sb + TG_A_LO + off);
            }
            if (nact) {
#pragma unroll
                for (int np = 0; np < 4; ++np) {
                    uint32_t boff = sw128((uint32_t)(((b_base + np * 16) << 7) +
                                                     ((ks * 16 + b_kof) << 1)));
                    uint32_t bh[4], bl[4];
                    ldsm4(bh, sb + TG_B_HI + boff);
                    ldsm4(bl, sb + TG_B_LO + boff);
#pragma unroll
                    for (int mt = 0; mt < 2; ++mt)
#pragma unroll
                        for (int h = 0; h < 2; ++h) {
                            float* d = acc[mt][np * 2 + h];
                            mma_bf(d, ah[mt], bh + h * 2);
                            mma_bf(d, ah[mt], bl + h * 2);
                            mma_bf(d, al[mt], bh + h * 2);
                        }
                }
            }
        }
    }

    // epilogue: relu(acc + be) -> atomic pool
    int orow = m0 + wm * 32 + (lane >> 2);
    int oc0  = n0 + wn * 64 + (lane & 3) * 2;
#pragma unroll
    for (int mt = 0; mt < 2; ++mt)
#pragma unroll
        for (int nt = 0; nt < 8; ++nt) {
            int col = oc0 + nt * 8;
            if (col >= HIDN) continue;
            float b0 = bvec[col], b1 = bvec[col + 1];
#pragma unroll
            for (int h = 0; h < 2; ++h) {
                int row = orow + mt * 16 + h * 8;
                if (row >= NNODES) continue;
                float* p = g_pool + batch[row] * HIDN + col;
                atomicAdd(p + 0, frelu(acc[mt][nt][h * 2] + b0));
                atomicAdd(p + 1, frelu(acc[mt][nt][h * 2 + 1] + b1));
            }
        }
}

// ---------------- FFN ----------------
__global__ void k_ffn(const float* __restrict__ Wf, const float* __restrict__ bf,
                      float* __restrict__ out) {
    int g = blockIdx.x;
    int lane = threadIdx.x;
    float s = 0.f;
    for (int k = lane; k < HIDN; k += 32) s += g_pool[g * HIDN + k] * Wf[k];
#pragma unroll
    for (int o = 16; o; o >>= 1) s += __shfl_xor_sync(0xffffffffu, s, o);
    if (lane == 0) out[g] = s + bf[0];
}

// ---------------- entry ----------------
extern "C" void kernel_launch(void* const* d_in, const int* in_sizes, int n_in,
                              void* d_out, int out_size) {
    const float* x     = (const float*)d_in[0];
    const float* ea    = (const float*)d_in[1];
    const int*   ei    = (const int*)d_in[2];
    const int*   rowi  = ei;
    const int*   coli  = ei + NEDGES;
    const int*   batch = (const int*)d_in[3];
    const float* Wi    = (const float*)d_in[4];
    const float* bi    = (const float*)d_in[5];
    const float* Wc    = (const float*)d_in[6];
    const float* bc    = (const float*)d_in[7];
    const float* We    = (const float*)d_in[8];
    const float* be    = (const float*)d_in[9];
    const float* Wf    = (const float*)d_in[10];
    const float* bf    = (const float*)d_in[11];
    float* out = (float*)d_out;

    cudaFuncSetAttribute(k_cgemm,  cudaFuncAttributeMaxDynamicSharedMemorySize, TG_TOTAL);
    cudaFuncSetAttribute(k_tginit, cudaFuncAttributeMaxDynamicSharedMemorySize, TG_TOTAL);
    cudaFuncSetAttribute(k_tgnode, cudaFuncAttributeMaxDynamicSharedMemorySize, TG_TOTAL);

    dim3 gT(3, NEDGES / 128);
    dim3 gN(3, (NNODES + 127) / 128);
    int ssB = (NNODES * 75 + 255) / 256;
    int hmB = (NEDGES * 80) / 256;

    k_pre<<<1440, 256>>>(Wc, Wi, We);                   // 1
    k_hist<<<NEDGES / 256, 256>>>(coli);                // 2
    k_tginit<<<gT, 256, TG_TOTAL>>>(rowi, bi, x, ea);   // 3: h0 + A bf16
    k_cgemm<<<gT, 256, TG_TOTAL>>>(0, 1);               // 4: t0  <- profiled
    k_scan<<<1, 1024>>>();                              // 5
    k_scatter<<<NEDGES / 256, 256>>>(coli);             // 6

    k_segsum<<<ssB, 256>>>(1);                          // u0
    k_hmat<<<hmB, 256>>>(1, bc, rowi);                  // A = h1 bf16
    k_cgemm<<<gT, 256, TG_TOTAL>>>(1, 2);               // t1
    k_segsum<<<ssB, 256>>>(2);                          // u1
    k_hmat<<<hmB, 256>>>(2, bc + HIDN, rowi);           // A = h2 bf16
    k_cgemm<<<gT, 256, TG_TOTAL>>>(2, 1);               // t2
    k_segsum<<<ssB, 256>>>(1);                          // u2
    k_segsum_h3<<<ssB, 256>>>(1, bc + 2 * HIDN, rowi);  // s (fused h3+segsum)

    k_tgnode<<<gN, 256, TG_TOTAL>>>(batch, be, x);      // node GEMM + pool
    k_ffn<<<NGRAPH, 32>>>(Wf, bf, out);
}

// round 9
// speedup vs baseline: 1.1209x; 1.0128x over previous
#include <cuda_runtime.h>
#include <cuda_bf16.h>
#include <cstdint>

#define NNODES 20000
#define NEDGES 320000
#define FNODE  64
#define FEDGE  16
#define HIDN   300
#define NGRAPH 128

typedef unsigned long long ull;

// ---------------- scratch (device globals) ----------------
__device__ float g_h0[NEDGES * HIDN];
__device__ float g_hA[NEDGES * HIDN];          // t ping
__device__ float g_hB[NEDGES * HIDN];          // t pong
__device__ __nv_bfloat16 g_Ah[NEDGES * 320];   // A operand hi (current layer)
__device__ __nv_bfloat16 g_Al[NEDGES * 320];   // A operand lo
__device__ float g_a [NNODES * HIDN];          // u2 (only final layer needs it stored)
__device__ float g_s [NNODES * HIDN];          // final node message
__device__ float g_pool[NGRAPH * HIDN];
__device__ __nv_bfloat16 g_Wh [3 * 384 * 320]; // conv W^T hi [l][n][k], zero-pad
__device__ __nv_bfloat16 g_Wl [3 * 384 * 320];
__device__ __nv_bfloat16 g_WIh[384 * 320];     // init W^T hi
__device__ __nv_bfloat16 g_WIl[384 * 320];
__device__ __nv_bfloat16 g_WNh[384 * 384];     // e2n W^T hi [n][k]
__device__ __nv_bfloat16 g_WNl[384 * 384];
__device__ int g_cnt [NNODES];
__device__ int g_ptr [NNODES + 1];
__device__ int g_fill[NNODES];
__device__ int g_eid [NEDGES];

__device__ __forceinline__ float* hbuf(int s) {
    return (s == 0) ? g_h0 : ((s == 1) ? g_hA : g_hB);
}

// ---------------- helpers ----------------
__device__ __forceinline__ float4 ld4(const float* p) { return *reinterpret_cast<const float4*>(p); }
__device__ __forceinline__ void   st4(float* p, float4 v) { *reinterpret_cast<float4*>(p) = v; }
__device__ __forceinline__ float  frelu(float x) { return x > 0.f ? x : 0.f; }

__device__ __forceinline__ uint32_t smem_u32(const void* p) {
    uint32_t a;
    asm("{ .reg .u64 t; cvta.to.shared.u64 t, %1; cvt.u32.u64 %0, t; }" : "=r"(a) : "l"(p));
    return a;
}
__device__ __forceinline__ uint32_t sw128(uint32_t o) { return o ^ ((o >> 3) & 0x70); }

__device__ __forceinline__ void ldsm4(uint32_t* r, uint32_t a) {
    asm volatile("ldmatrix.sync.aligned.m8n8.x4.shared.b16 {%0,%1,%2,%3}, [%4];"
                 : "=r"(r[0]), "=r"(r[1]), "=r"(r[2]), "=r"(r[3]) : "r"(a));
}
__device__ __forceinline__ void mma_bf(float* d, const uint32_t* a, const uint32_t* b) {
    asm volatile("mma.sync.aligned.m16n8k16.row.col.f32.bf16.bf16.f32 "
                 "{%0,%1,%2,%3}, {%4,%5,%6,%7}, {%8,%9}, {%0,%1,%2,%3};"
                 : "+f"(d[0]), "+f"(d[1]), "+f"(d[2]), "+f"(d[3])
                 : "r"(a[0]), "r"(a[1]), "r"(a[2]), "r"(a[3]), "r"(b[0]), "r"(b[1]));
}
#define CPA16(dst, src) asm volatile("cp.async.cg.shared.global [%0], [%1], 16;" :: "r"(dst), "l"(src))
#define CPA_COMMIT()    asm volatile("cp.async.commit_group;" ::: "memory")
#define CPA_WAIT0()     asm volatile("cp.async.wait_group 0;" ::: "memory")

__device__ __forceinline__ void split_pack(float v0, float v1, uint32_t& hi, uint32_t& lo) {
    __nv_bfloat162 h, l;
    h.x = __float2bfloat16(v0); h.y = __float2bfloat16(v1);
    l.x = __float2bfloat16(v0 - __bfloat162float(h.x));
    l.y = __float2bfloat16(v1 - __bfloat162float(h.y));
    hi = *reinterpret_cast<uint32_t*>(&h);
    lo = *reinterpret_cast<uint32_t*>(&l);
}

// ---------------- preprocessing ----------------
__global__ void k_pre(const float* __restrict__ Wc, const float* __restrict__ Wi,
                      const float* __restrict__ We) {
    int t = blockIdx.x * blockDim.x + threadIdx.x;
    if (t < NNODES) g_cnt[t] = 0;
    if (t < NGRAPH * HIDN) g_pool[t] = 0.f;
    if (t < 122880) {
        int n = t / 320, k = t % 320;
        float v = (n < HIDN && k < 80) ? Wi[k * HIDN + n] : 0.f;
        __nv_bfloat16 bh = __float2bfloat16(v);
        g_WIh[t] = bh;
        g_WIl[t] = __float2bfloat16(v - __bfloat162float(bh));
    }
    if (t < 3 * 122880) {
        int l = t / 122880, r2 = t % 122880;
        int n = r2 / 320, k = r2 % 320;
        float v = (n < HIDN && k < HIDN) ? Wc[l * HIDN * HIDN + k * HIDN + n] : 0.f;
        __nv_bfloat16 bh = __float2bfloat16(v);
        g_Wh[t] = bh;
        g_Wl[t] = __float2bfloat16(v - __bfloat162float(bh));
    }
    if (t < 384 * 384) {
        int n = t / 384, k = t % 384;
        float v = (n < HIDN && k < FNODE + HIDN) ? We[k * HIDN + n] : 0.f;
        __nv_bfloat16 bh = __float2bfloat16(v);
        g_WNh[t] = bh;
        g_WNl[t] = __float2bfloat16(v - __bfloat162float(bh));
    }
}

__global__ void k_hist(const int* __restrict__ coli) {
    int e = blockIdx.x * blockDim.x + threadIdx.x;
    if (e < NEDGES) atomicAdd(&g_cnt[coli[e]], 1);
}

__global__ void k_scan() {
    __shared__ int sh[1024];
    int tid = threadIdx.x;
    int carry = 0;
    const int CH = (NNODES + 1023) / 1024;
    for (int c = 0; c < CH; ++c) {
        int i = c * 1024 + tid;
        int v = (i < NNODES) ? g_cnt[i] : 0;
        sh[tid] = v;
        __syncthreads();
        for (int off = 1; off < 1024; off <<= 1) {
            int t = (tid >= off) ? sh[tid - off] : 0;
            __syncthreads();
            sh[tid] += t;
            __syncthreads();
        }
        int inc = sh[tid];
        int total = sh[1023];
        if (i < NNODES) {
            int ex = carry + inc - v;
            g_ptr[i]  = ex;
            g_fill[i] = ex;
        }
        carry += total;
        __syncthreads();
    }
    if (tid == 0) g_ptr[NNODES] = carry;
}

__global__ void k_scatter(const int* __restrict__ coli) {
    int e = blockIdx.x * blockDim.x + threadIdx.x;
    if (e < NEDGES) {
        int pos = atomicAdd(&g_fill[coli[e]], 1);
        g_eid[pos] = e;
    }
}

// ---------------- segment sum: g_a[n] = sum t[e] (used for u2 only) ----------
__global__ void k_segsum(int src_sel) {
    const float* h = hbuf(src_sel);
    int t = blockIdx.x * blockDim.x + threadIdx.x;
    if (t >= NNODES * 75) return;
    int n = t / 75;
    int c = (t - n * 75) * 4;
    int beg = g_ptr[n], end = g_ptr[n + 1];
    float4 acc = make_float4(0.f, 0.f, 0.f, 0.f);
#pragma unroll 2
    for (int i = beg; i < end; ++i) {
        int e = g_eid[i];
        float4 vv = ld4(h + e * HIDN + c);
        acc.x += vv.x; acc.y += vv.y; acc.z += vv.z; acc.w += vv.w;
    }
    st4(g_a + n * HIDN + c, acc);
}

// ------ fused segsum + next-h materialize -------------------------------
// For node n, in-edges e (col[e]==n): u = sum t[e]. The out-edges needing
// u[n] are exactly e^1 (paired reverse). Pass 2 writes
// h_next[e^1] = relu(h0[e^1] + bc + u - t[e]) as bf16 hi/lo into g_Ah/g_Al.
__global__ void k_seghm(int t_sel, const float* __restrict__ bc) {
    const float* tp = hbuf(t_sel);
    int t = blockIdx.x * blockDim.x + threadIdx.x;
    if (t >= NNODES * 75) return;
    int n = t / 75;
    int c = (t - n * 75) * 4;
    float4 bv = ld4(bc + c);
    int beg = g_ptr[n], end = g_ptr[n + 1];
    float4 u = make_float4(0.f, 0.f, 0.f, 0.f);
#pragma unroll 2
    for (int i = beg; i < end; ++i) {
        int e = g_eid[i];
        float4 vv = ld4(tp + e * HIDN + c);
        u.x += vv.x; u.y += vv.y; u.z += vv.z; u.w += vv.w;
    }
    for (int i = beg; i < end; ++i) {
        int e = g_eid[i];
        int er = e ^ 1;
        float4 tv  = ld4(tp + e * HIDN + c);        // L1/L2-hot from pass 1
        float4 h0v = ld4(g_h0 + er * HIDN + c);
        float4 v;
        v.x = frelu(h0v.x + bv.x + u.x - tv.x);
        v.y = frelu(h0v.y + bv.y + u.y - tv.y);
        v.z = frelu(h0v.z + bv.z + u.z - tv.z);
        v.w = frelu(h0v.w + bv.w + u.w - tv.w);
        uint32_t h0w, l0w, h1w, l1w;
        split_pack(v.x, v.y, h0w, l0w);
        split_pack(v.z, v.w, h1w, l1w);
        *reinterpret_cast<uint2*>(g_Ah + (size_t)er * 320 + c) = make_uint2(h0w, h1w);
        *reinterpret_cast<uint2*>(g_Al + (size_t)er * 320 + c) = make_uint2(l0w, l1w);
    }
}

// --------- fused final: g_s[n] = sum_e relu(h0[e]+bc2+u2[row[e]]-rev(t2)) ----
__global__ void k_segsum_h3(int t2_sel, const float* __restrict__ bc2,
                            const int* __restrict__ rowi) {
    const float* t2 = hbuf(t2_sel);
    int t = blockIdx.x * blockDim.x + threadIdx.x;
    if (t >= NNODES * 75) return;
    int n = t / 75;
    int c = (t - n * 75) * 4;
    float4 bv = ld4(bc2 + c);
    int beg = g_ptr[n], end = g_ptr[n + 1];
    float4 acc = make_float4(0.f, 0.f, 0.f, 0.f);
#pragma unroll 2
    for (int i = beg; i < end; ++i) {
        int e = g_eid[i];
        float4 h0v = ld4(g_h0 + e * HIDN + c);
        float4 uv  = ld4(g_a + rowi[e] * HIDN + c);
        float4 tv  = ld4(t2 + (e ^ 1) * HIDN + c);
        acc.x += frelu(h0v.x + bv.x + uv.x - tv.x);
        acc.y += frelu(h0v.y + bv.y + uv.y - tv.y);
        acc.z += frelu(h0v.z + bv.z + uv.z - tv.z);
        acc.w += frelu(h0v.w + bv.w + uv.w - tv.w);
    }
    st4(g_s + n * HIDN + c, acc);
}

// =====================================================================
// Pure conv GEMM (R6-proven): t_out = A @ W_layer, K=320 in 5 chunks of 64.
// CTA 128m x 128n, 8 warps (4m x 2n), SW128, cp.async, 3-pass bf16 split.
// =====================================================================
#define TG_A_HI 0
#define TG_A_LO 16384
#define TG_B_HI 32768
#define TG_B_LO 49152
#define TG_TOTAL 65536

__global__ void __launch_bounds__(256, 2) k_cgemm(int layer, int out_sel) {
    extern __shared__ char smem[];
    uint32_t sb = smem_u32(smem);
    int tid = threadIdx.x;
    int lane = tid & 31;
    int wid = tid >> 5;
    int m0 = blockIdx.y * 128;
    int n0 = blockIdx.x * 128;

    const __nv_bfloat16* Wh = g_Wh + layer * 122880;
    const __nv_bfloat16* Wl = g_Wl + layer * 122880;
    float* tout = hbuf(out_sel);

    int wm = wid >> 1, wn = wid & 1;
    int mat = lane >> 3, l7 = lane & 7;
    int a_row = wm * 32 + (mat & 1) * 8 + l7;
    int a_kof = (mat >> 1) * 8;
    int b_base = wn * 64 + (mat >> 1) * 8 + l7;
    int b_kof = (mat & 1) * 8;
    bool nact = (n0 + wn * 64) < HIDN;

    float acc[2][8][4];
#pragma unroll
    for (int i = 0; i < 2; i++)
#pragma unroll
        for (int j = 0; j < 8; j++)
#pragma unroll
            for (int q = 0; q < 4; q++) acc[i][j][q] = 0.f;

    for (int kc = 0; kc < 5; ++kc) {
        int k0 = kc * 64;
        if (kc) __syncthreads();
#pragma unroll
        for (int s = 0; s < 4; s++) {
            int j = tid + s * 256;
            int r2 = j >> 3, i = j & 7;
            uint32_t off = sw128((uint32_t)(r2 * 128 + i * 16));
            CPA16(sb + TG_A_HI + off, g_Ah + (size_t)(m0 + r2) * 320 + k0 + i * 8);
            CPA16(sb + TG_A_LO + off, g_Al + (size_t)(m0 + r2) * 320 + k0 + i * 8);
        }
#pragma unroll
        for (int s = 0; s < 4; s++) {
            int j = tid + s * 256;
            int n = j >> 3, i = j & 7;
            uint32_t off = sw128((uint32_t)(n * 128 + i * 16));
            CPA16(sb + TG_B_HI + off, Wh + (n0 + n) * 320 + k0 + i * 8);
            CPA16(sb + TG_B_LO + off, Wl + (n0 + n) * 320 + k0 + i * 8);
        }
        CPA_COMMIT();
        CPA_WAIT0();
        __syncthreads();

#pragma unroll
        for (int ks = 0; ks < 4; ++ks) {
            uint32_t ah[2][4], al[2][4];
#pragma unroll
            for (int mt = 0; mt < 2; ++mt) {
                uint32_t off = sw128((uint32_t)(((a_row + mt * 16) << 7) +
                                                ((ks * 16 + a_kof) << 1)));
                ldsm4(ah[mt], sb + TG_A_HI + off);
                ldsm4(al[mt], sb + TG_A_LO + off);
            }
            if (nact) {
#pragma unroll
                for (int np = 0; np < 4; ++np) {
                    uint32_t boff = sw128((uint32_t)(((b_base + np * 16) << 7) +
                                                     ((ks * 16 + b_kof) << 1)));
                    uint32_t bh[4], bl[4];
                    ldsm4(bh, sb + TG_B_HI + boff);
                    ldsm4(bl, sb + TG_B_LO + boff);
#pragma unroll
                    for (int mt = 0; mt < 2; ++mt)
#pragma unroll
                        for (int h = 0; h < 2; ++h) {
                            float* d = acc[mt][np * 2 + h];
                            mma_bf(d, ah[mt], bh + h * 2);
                            mma_bf(d, ah[mt], bl + h * 2);
                            mma_bf(d, al[mt], bh + h * 2);
                        }
                }
            }
        }
    }

    int orow = m0 + wm * 32 + (lane >> 2);
    int oc0  = n0 + wn * 64 + (lane & 3) * 2;
#pragma unroll
    for (int mt = 0; mt < 2; ++mt)
#pragma unroll
        for (int nt = 0; nt < 8; ++nt) {
            int col = oc0 + nt * 8;
            if (col >= HIDN) continue;
#pragma unroll
            for (int h = 0; h < 2; ++h) {
                int row = orow + mt * 16 + h * 8;
                *reinterpret_cast<float2*>(tout + row * HIDN + col) =
                    make_float2(acc[mt][nt][h * 2], acc[mt][nt][h * 2 + 1]);
            }
        }
}

// =====================================================================
// Init GEMM: A = [x[row]|ea] (K=80 -> 2 chunks), epilogue h0 fp32 + bf16 split
// =====================================================================
__global__ void __launch_bounds__(256, 2) k_tginit(
    const int* __restrict__ rowi, const float* __restrict__ bvec,
    const float* __restrict__ x, const float* __restrict__ ea)
{
    extern __shared__ char smem[];
    uint32_t sb = smem_u32(smem);
    int tid = threadIdx.x;
    int lane = tid & 31;
    int wid = tid >> 5;
    int m0 = blockIdx.y * 128;
    int n0 = blockIdx.x * 128;

    int r = tid >> 1;
    int e = m0 + r;
    int cc0 = (tid & 1) * 32;
    int rv = rowi[e];

    int wm = wid >> 1, wn = wid & 1;
    int mat = lane >> 3, l7 = lane & 7;
    int a_row = wm * 32 + (mat & 1) * 8 + l7;
    int a_kof = (mat >> 1) * 8;
    int b_base = wn * 64 + (mat >> 1) * 8 + l7;
    int b_kof = (mat & 1) * 8;
    bool nact = (n0 + wn * 64) < HIDN;

    float acc[2][8][4];
#pragma unroll
    for (int i = 0; i < 2; i++)
#pragma unroll
        for (int j = 0; j < 8; j++)
#pragma unroll
            for (int q = 0; q < 4; q++) acc[i][j][q] = 0.f;

    for (int kc = 0; kc < 2; ++kc) {
        int k0 = kc * 64;
        if (kc) __syncthreads();
#pragma unroll
        for (int s = 0; s < 4; s++) {
            int j = tid + s * 256;
            int n = j >> 3, i = j & 7;
            uint32_t off = sw128((uint32_t)(n * 128 + i * 16));
            CPA16(sb + TG_B_HI + off, g_WIh + (n0 + n) * 320 + k0 + i * 8);
            CPA16(sb + TG_B_LO + off, g_WIl + (n0 + n) * 320 + k0 + i * 8);
        }
        CPA_COMMIT();
#pragma unroll
        for (int i = 0; i < 8; i++) {
            int cc = cc0 + i * 4;
            int k = k0 + cc;
            float4 v = make_float4(0.f, 0.f, 0.f, 0.f);
            if (k < FNODE)    v = ld4(x + rv * FNODE + k);
            else if (k < 80)  v = ld4(ea + e * FEDGE + (k - FNODE));
            uint32_t h0w, l0w, h1w, l1w;
            split_pack(v.x, v.y, h0w, l0w);
            split_pack(v.z, v.w, h1w, l1w);
            uint32_t off = sw128((uint32_t)(r * 128 + cc * 2));
            *reinterpret_cast<uint2*>(smem + TG_A_HI + off) = make_uint2(h0w, h1w);
            *reinterpret_cast<uint2*>(smem + TG_A_LO + off) = make_uint2(l0w, l1w);
        }
        CPA_WAIT0();
        __syncthreads();
#pragma unroll
        for (int ks = 0; ks < 4; ++ks) {
            uint32_t ah[2][4], al[2][4];
#pragma unroll
            for (int mt = 0; mt < 2; ++mt) {
                uint32_t off = sw128((uint32_t)(((a_row + mt * 16) << 7) +
                                                ((ks * 16 + a_kof) << 1)));
                ldsm4(ah[mt], sb + TG_A_HI + off);
                ldsm4(al[mt], sb + TG_A_LO + off);
            }
            if (nact) {
#pragma unroll
                for (int np = 0; np < 4; ++np) {
                    uint32_t boff = sw128((uint32_t)(((b_base + np * 16) << 7) +
                                                     ((ks * 16 + b_kof) << 1)));
                    uint32_t bh[4], bl[4];
                    ldsm4(bh, sb + TG_B_HI + boff);
                    ldsm4(bl, sb + TG_B_LO + boff);
#pragma unroll
                    for (int mt = 0; mt < 2; ++mt)
#pragma unroll
                        for (int h = 0; h < 2; ++h) {
                            float* d = acc[mt][np * 2 + h];
                            mma_bf(d, ah[mt], bh + h * 2);
                            mma_bf(d, ah[mt], bl + h * 2);
                            mma_bf(d, al[mt], bh + h * 2);
                        }
                }
            }
        }
    }

    int orow = m0 + wm * 32 + (lane >> 2);
    int oc0  = n0 + wn * 64 + (lane & 3) * 2;
#pragma unroll
    for (int mt = 0; mt < 2; ++mt)
#pragma unroll
        for (int nt = 0; nt < 8; ++nt) {
            int col = oc0 + nt * 8;
            if (col >= 320) continue;
            bool live = col < HIDN;
            float b0 = live ? bvec[col] : 0.f;
            float b1 = live ? bvec[col + 1] : 0.f;
#pragma unroll
            for (int h = 0; h < 2; ++h) {
                int row = orow + mt * 16 + h * 8;
                float v0 = live ? frelu(acc[mt][nt][h * 2] + b0) : 0.f;
                float v1 = live ? frelu(acc[mt][nt][h * 2 + 1] + b1) : 0.f;
                if (live)
                    *reinterpret_cast<float2*>(g_h0 + row * HIDN + col) = make_float2(v0, v1);
                uint32_t hw, lw;
                split_pack(v0, v1, hw, lw);
                *reinterpret_cast<uint32_t*>(g_Ah + (size_t)row * 320 + col) = hw;
                *reinterpret_cast<uint32_t*>(g_Al + (size_t)row * 320 + col) = lw;
            }
        }
}

// =====================================================================
// Node GEMM (tensor): hn = relu([x|s] @ W_e2n + be); pool += hn
// =====================================================================
__global__ void __launch_bounds__(256, 2) k_tgnode(
    const int* __restrict__ batch, const float* __restrict__ bvec,
    const float* __restrict__ x)
{
    extern __shared__ char smem[];
    uint32_t sb = smem_u32(smem);
    int tid = threadIdx.x;
    int lane = tid & 31;
    int wid = tid >> 5;
    int m0 = blockIdx.y * 128;
    int n0 = blockIdx.x * 128;

    int r = tid >> 1;
    int e = m0 + r;
    bool eok = (e < NNODES);
    int es = eok ? e : 0;
    int cc0 = (tid & 1) * 32;

    int wm = wid >> 1, wn = wid & 1;
    int mat = lane >> 3, l7 = lane & 7;
    int a_row = wm * 32 + (mat & 1) * 8 + l7;
    int a_kof = (mat >> 1) * 8;
    int b_base = wn * 64 + (mat >> 1) * 8 + l7;
    int b_kof = (mat & 1) * 8;
    bool nact = (n0 + wn * 64) < HIDN;

    const int KTOT = FNODE + HIDN;  // 364

    float acc[2][8][4];
#pragma unroll
    for (int i = 0; i < 2; i++)
#pragma unroll
        for (int j = 0; j < 8; j++)
#pragma unroll
            for (int q = 0; q < 4; q++) acc[i][j][q] = 0.f;

    for (int kc = 0; kc < 6; ++kc) {
        int k0 = kc * 64;
        if (kc) __syncthreads();
#pragma unroll
        for (int s = 0; s < 4; s++) {
            int j = tid + s * 256;
            int n = j >> 3, i = j & 7;
            uint32_t off = sw128((uint32_t)(n * 128 + i * 16));
            CPA16(sb + TG_B_HI + off, g_WNh + (n0 + n) * 384 + k0 + i * 8);
            CPA16(sb + TG_B_LO + off, g_WNl + (n0 + n) * 384 + k0 + i * 8);
        }
        CPA_COMMIT();
#pragma unroll
        for (int i = 0; i < 8; i++) {
            int cc = cc0 + i * 4;
            int k = k0 + cc;
            float4 v = make_float4(0.f, 0.f, 0.f, 0.f);
            if (eok && k < KTOT)
                v = (k < FNODE) ? ld4(x + es * FNODE + k)
                                : ld4(g_s + es * HIDN + (k - FNODE));
            uint32_t h0w, l0w, h1w, l1w;
            split_pack(v.x, v.y, h0w, l0w);
            split_pack(v.z, v.w, h1w, l1w);
            uint32_t off = sw128((uint32_t)(r * 128 + cc * 2));
            *reinterpret_cast<uint2*>(smem + TG_A_HI + off) = make_uint2(h0w, h1w);
            *reinterpret_cast<uint2*>(smem + TG_A_LO + off) = make_uint2(l0w, l1w);
        }
        CPA_WAIT0();
        __syncthreads();
#pragma unroll
        for (int ks = 0; ks < 4; ++ks) {
            uint32_t ah[2][4], al[2][4];
#pragma unroll
            for (int mt = 0; mt < 2; ++mt) {
                uint32_t off = sw128((uint32_t)(((a_row + mt * 16) << 7) +
                                                ((ks * 16 + a_kof) << 1)));
                ldsm4(ah[mt], sb + TG_A_HI + off);
                ldsm4(al[mt], sb + TG_A_LO + off);
            }
            if (nact) {
#pragma unroll
                for (int np = 0; np < 4; ++np) {
                    uint32_t boff = sw128((uint32_t)(((b_base + np * 16) << 7) +
                                                     ((ks * 16 + b_kof) << 1)));
                    uint32_t bh[4], bl[4];
                    ldsm4(bh, sb + TG_B_HI + boff);
                    ldsm4(bl, sb + TG_B_LO + boff);
#pragma unroll
                    for (int mt = 0; mt < 2; ++mt)
#pragma unroll
                        for (int h = 0; h < 2; ++h) {
                            float* d = acc[mt][np * 2 + h];
                            mma_bf(d, ah[mt], bh + h * 2);
                            mma_bf(d, ah[mt], bl + h * 2);
                            mma_bf(d, al[mt], bh + h * 2);
                        }
                }
            }
        }
    }

    int orow = m0 + wm * 32 + (lane >> 2);
    int oc0  = n0 + wn * 64 + (lane & 3) * 2;
#pragma unroll
    for (int mt = 0; mt < 2; ++mt)
#pragma unroll
        for (int nt = 0; nt < 8; ++nt) {
            int col = oc0 + nt * 8;
            if (col >= HIDN) continue;
            float b0 = bvec[col], b1 = bvec[col + 1];
#pragma unroll
            for (int h = 0; h < 2; ++h) {
                int row = orow + mt * 16 + h * 8;
                if (row >= NNODES) continue;
                float* p = g_pool + batch[row] * HIDN + col;
                atomicAdd(p + 0, frelu(acc[mt][nt][h * 2] + b0));
                atomicAdd(p + 1, frelu(acc[mt][nt][h * 2 + 1] + b1));
            }
        }
}

// ---------------- FFN ----------------
__global__ void k_ffn(const float* __restrict__ Wf, const float* __restrict__ bf,
                      float* __restrict__ out) {
    int g = blockIdx.x;
    int lane = threadIdx.x;
    float s = 0.f;
    for (int k = lane; k < HIDN; k += 32) s += g_pool[g * HIDN + k] * Wf[k];
#pragma unroll
    for (int o = 16; o; o >>= 1) s += __shfl_xor_sync(0xffffffffu, s, o);
    if (lane == 0) out[g] = s + bf[0];
}

// ---------------- entry ----------------
extern "C" void kernel_launch(void* const* d_in, const int* in_sizes, int n_in,
                              void* d_out, int out_size) {
    const float* x     = (const float*)d_in[0];
    const float* ea    = (const float*)d_in[1];
    const int*   ei    = (const int*)d_in[2];
    const int*   rowi  = ei;
    const int*   coli  = ei + NEDGES;
    const int*   batch = (const int*)d_in[3];
    const float* Wi    = (const float*)d_in[4];
    const float* bi    = (const float*)d_in[5];
    const float* Wc    = (const float*)d_in[6];
    const float* bc    = (const float*)d_in[7];
    const float* We    = (const float*)d_in[8];
    const float* be    = (const float*)d_in[9];
    const float* Wf    = (const float*)d_in[10];
    const float* bf    = (const float*)d_in[11];
    float* out = (float*)d_out;

    cudaFuncSetAttribute(k_cgemm,  cudaFuncAttributeMaxDynamicSharedMemorySize, TG_TOTAL);
    cudaFuncSetAttribute(k_tginit, cudaFuncAttributeMaxDynamicSharedMemorySize, TG_TOTAL);
    cudaFuncSetAttribute(k_tgnode, cudaFuncAttributeMaxDynamicSharedMemorySize, TG_TOTAL);

    dim3 gT(3, NEDGES / 128);
    dim3 gN(3, (NNODES + 127) / 128);
    int ssB = (NNODES * 75 + 255) / 256;

    k_pre<<<1440, 256>>>(Wc, Wi, We);                   // 1
    k_hist<<<NEDGES / 256, 256>>>(coli);                // 2
    k_tginit<<<gT, 256, TG_TOTAL>>>(rowi, bi, x, ea);   // 3: h0 + A bf16
    k_cgemm<<<gT, 256, TG_TOTAL>>>(0, 1);               // 4: t0  <- profiled
    k_scan<<<1, 1024>>>();                              // 5
    k_scatter<<<NEDGES / 256, 256>>>(coli);             // 6

    k_seghm<<<ssB, 256>>>(1, bc);                       // u0 (regs) + A = h1 bf16
    k_cgemm<<<gT, 256, TG_TOTAL>>>(1, 2);               // t1
    k_seghm<<<ssB, 256>>>(2, bc + HIDN);                // u1 (regs) + A = h2 bf16
    k_cgemm<<<gT, 256, TG_TOTAL>>>(2, 1);               // t2
    k_segsum<<<ssB, 256>>>(1);                          // u2 -> g_a
    k_segsum_h3<<<ssB, 256>>>(1, bc + 2 * HIDN, rowi);  // s (fused h3+segsum)

    k_tgnode<<<gN, 256, TG_TOTAL>>>(batch, be, x);      // node GEMM + pool
    k_ffn<<<NGRAPH, 32>>>(Wf, bf, out);
}